// round 12
// baseline (speedup 1.0000x reference)
#include <cuda_runtime.h>
#include <cuda_bf16.h>
#include <cstdint>
#include <math.h>

#define BB 2
#define SS 2048
#define DM 1024
#define NH 16
#define DKH 64
#define DFF 2688
#define ROWS (BB*SS)   // 4096

// ---- fp32 scratch ----
__device__ float g_q  [ROWS*DM];
__device__ float g_k  [ROWS*DM];
__device__ float g_v  [ROWS*DM];
__device__ float g_x1 [ROWS*DM];
__device__ float g_gt [ROWS*DFF];
__device__ float g_up [ROWS*DFF];
// ---- bf16 split scratch (hi/lo) ----
__device__ __nv_bfloat16 g_h_h [ROWS*DM],  g_h_l [ROWS*DM];
__device__ __nv_bfloat16 g_cx_h[ROWS*DM],  g_cx_l[ROWS*DM];
__device__ __nv_bfloat16 g_gl_h[ROWS*DFF], g_gl_l[ROWS*DFF];
__device__ __nv_bfloat16 g_wq_h[DM*DM],  g_wq_l[DM*DM];
__device__ __nv_bfloat16 g_wk_h[DM*DM],  g_wk_l[DM*DM];
__device__ __nv_bfloat16 g_wv_h[DM*DM],  g_wv_l[DM*DM];
__device__ __nv_bfloat16 g_wo_h[DM*DM],  g_wo_l[DM*DM];
__device__ __nv_bfloat16 g_w1_h[DFF*DM], g_w1_l[DFF*DM];
__device__ __nv_bfloat16 g_w3_h[DFF*DM], g_w3_l[DFF*DM];
__device__ __nv_bfloat16 g_w2_h[DM*DFF], g_w2_l[DM*DFF];

// ================= helpers =================
__device__ __forceinline__ uint32_t smem_u32(const void* p) {
    uint32_t a;
    asm("{ .reg .u64 t; cvta.to.shared.u64 t, %1; cvt.u32.u64 %0, t; }" : "=r"(a) : "l"(p));
    return a;
}
__device__ __forceinline__ uint32_t pk2(__nv_bfloat16 a, __nv_bfloat16 b) {
    return (uint32_t)__bfloat16_as_ushort(a) | ((uint32_t)__bfloat16_as_ushort(b) << 16);
}
__device__ __forceinline__ void split1(float x, __nv_bfloat16& h, __nv_bfloat16& l) {
    h = __float2bfloat16(x);
    l = __float2bfloat16(x - __bfloat162float(h));
}
__device__ __forceinline__ void ldm4(uint32_t* r, uint32_t addr) {
    asm volatile("ldmatrix.sync.aligned.m8n8.x4.shared.b16 {%0,%1,%2,%3}, [%4];"
        : "=r"(r[0]), "=r"(r[1]), "=r"(r[2]), "=r"(r[3]) : "r"(addr));
}
__device__ __forceinline__ void ldm4t(uint32_t* r, uint32_t addr) {
    asm volatile("ldmatrix.sync.aligned.m8n8.x4.trans.shared.b16 {%0,%1,%2,%3}, [%4];"
        : "=r"(r[0]), "=r"(r[1]), "=r"(r[2]), "=r"(r[3]) : "r"(addr));
}
__device__ __forceinline__ void mma16816(float* d, const uint32_t* a, const uint32_t* b) {
    asm volatile("mma.sync.aligned.m16n8k16.row.col.f32.bf16.bf16.f32 "
        "{%0,%1,%2,%3},{%4,%5,%6,%7},{%8,%9},{%0,%1,%2,%3};"
        : "+f"(d[0]), "+f"(d[1]), "+f"(d[2]), "+f"(d[3])
        : "r"(a[0]), "r"(a[1]), "r"(a[2]), "r"(a[3]), "r"(b[0]), "r"(b[1]));
}
__device__ __forceinline__ void cpasync16(uint32_t saddr, const void* gaddr) {
    asm volatile("cp.async.cg.shared.global [%0], [%1], 16;" :: "r"(saddr), "l"(gaddr));
}
#define CP_COMMIT() asm volatile("cp.async.commit_group;" ::: "memory")
#define CP_WAIT1()  asm volatile("cp.async.wait_group 1;" ::: "memory")
// 8 fp32 -> packed bf16 hi/lo uint4
__device__ __forceinline__ void cvt8(const float4& u, const float4& v, uint4& hi, uint4& lo) {
    __nv_bfloat16 h0,l0,h1,l1,h2,l2,h3,l3,h4,l4,h5,l5,h6,l6,h7,l7;
    split1(u.x,h0,l0); split1(u.y,h1,l1); split1(u.z,h2,l2); split1(u.w,h3,l3);
    split1(v.x,h4,l4); split1(v.y,h5,l5); split1(v.z,h6,l6); split1(v.w,h7,l7);
    hi = make_uint4(pk2(h0,h1), pk2(h2,h3), pk2(h4,h5), pk2(h6,h7));
    lo = make_uint4(pk2(l0,l1), pk2(l2,l3), pk2(l4,l5), pk2(l6,l7));
}

// ================= merged split kernels: fp32 -> bf16 hi/lo (MLP=4) =================
__device__ __forceinline__ void split_body(const float4* in, uint2* hi, uint2* lo, int i) {
    float4 v = in[i];
    __nv_bfloat16 hx, lx, hy, ly, hz, lz, hw, lw;
    split1(v.x, hx, lx); split1(v.y, hy, ly);
    split1(v.z, hz, lz); split1(v.w, hw, lw);
    hi[i] = make_uint2(pk2(hx, hy), pk2(hz, hw));
    lo[i] = make_uint2(pk2(lx, ly), pk2(lz, lw));
}
__global__ __launch_bounds__(256) void split4_kernel(
    const float4* a, const float4* b, const float4* c, const float4* d,
    uint2* ah, uint2* al, uint2* bh, uint2* bl,
    uint2* ch, uint2* cl, uint2* dh, uint2* dl, int n4) {
    int base = blockIdx.x * 1024 + threadIdx.x;
    int w = blockIdx.y;
    const float4* in = (w == 0) ? a : (w == 1) ? b : (w == 2) ? c : d;
    uint2* hi = (w == 0) ? ah : (w == 1) ? bh : (w == 2) ? ch : dh;
    uint2* lo = (w == 0) ? al : (w == 1) ? bl : (w == 2) ? cl : dl;
    #pragma unroll
    for (int it = 0; it < 4; it++) {
        int i = base + it * 256;
        if (i < n4) split_body(in, hi, lo, i);
    }
}
__global__ __launch_bounds__(256) void split3_kernel(
    const float4* a, const float4* b, const float4* c,
    uint2* ah, uint2* al, uint2* bh, uint2* bl, uint2* ch, uint2* cl, int n4) {
    int base = blockIdx.x * 1024 + threadIdx.x;
    int w = blockIdx.y;
    const float4* in = (w == 0) ? a : (w == 1) ? b : c;
    uint2* hi = (w == 0) ? ah : (w == 1) ? bh : ch;
    uint2* lo = (w == 0) ? al : (w == 1) ? bl : cl;
    #pragma unroll
    for (int it = 0; it < 4; it++) {
        int i = base + it * 256;
        if (i < n4) split_body(in, hi, lo, i);
    }
}

// ================= MMA GEMM: C[M,N] = A[M,K] @ W[N,K]^T (+R, +RoPE) =================
// 128x128x64 tiles, 3-stage cp.async pipeline, 512 threads, bf16 3-product.
// Product-major MMA ordering: dependent MMAs 8 issues apart.
#define KC 64
#define GSTAGES 3
#define GSTAGE_BYTES 65536
#define GSMEM (GSTAGES*GSTAGE_BYTES) // 196608

template<int EPI>
__global__ __launch_bounds__(512, 1) void mma_gemm(
    const __nv_bfloat16* __restrict__ Ah, const __nv_bfloat16* __restrict__ Al,
    const __nv_bfloat16* __restrict__ Bh0, const __nv_bfloat16* __restrict__ Bl0,
    const __nv_bfloat16* __restrict__ Bh1, const __nv_bfloat16* __restrict__ Bl1,
    const __nv_bfloat16* __restrict__ Bh2, const __nv_bfloat16* __restrict__ Bl2,
    const float* __restrict__ R, const int* __restrict__ posp,
    float* __restrict__ C0, float* __restrict__ C1, float* __restrict__ C2,
    int M, int N, int K)
{
    extern __shared__ uint4 sm4[];
    uint32_t smb = smem_u32(sm4);
    int tid = threadIdx.x, lane = tid & 31, wid = tid >> 5;
    int wm = wid & 3, wn = wid >> 2;
    int mBase = blockIdx.y * 128, nBase = blockIdx.x * 128;
    int z = blockIdx.z;
    const __nv_bfloat16* Bh = (z == 0) ? Bh0 : (z == 1) ? Bh1 : Bh2;
    const __nv_bfloat16* Bl = (z == 0) ? Bl0 : (z == 1) ? Bl1 : Bl2;
    float* C = (z == 0) ? C0 : (z == 1) ? C1 : C2;

    int lr = tid >> 2, lc = tid & 3;
    const __nv_bfloat16* pAh = Ah + (size_t)(mBase + lr) * K;
    const __nv_bfloat16* pAl = Al + (size_t)(mBase + lr) * K;
    const __nv_bfloat16* pBh = Bh + (size_t)(nBase + lr) * K;
    const __nv_bfloat16* pBl = Bl + (size_t)(nBase + lr) * K;
    int xr8 = lr & 7;
    uint32_t rbase = smb + (uint32_t)lr * 128;

    auto issue_stage = [&](int st) {
        int k0 = st * KC;
        uint32_t d = rbase + (uint32_t)(st % GSTAGES) * GSTAGE_BYTES;
        #pragma unroll
        for (int c = 0; c < 2; c++) {
            int ch = lc + c * 4;
            uint32_t so = (uint32_t)(ch ^ xr8) * 16;
            cpasync16(d + so,         pAh + k0 + ch * 8);
            cpasync16(d + 16384 + so, pAl + k0 + ch * 8);
            cpasync16(d + 32768 + so, pBh + k0 + ch * 8);
            cpasync16(d + 49152 + so, pBl + k0 + ch * 8);
        }
    };

    float acc[2][4][4];
    #pragma unroll
    for (int a = 0; a < 2; a++)
        #pragma unroll
        for (int b = 0; b < 4; b++)
            #pragma unroll
            for (int c = 0; c < 4; c++) acc[a][b][c] = 0.0f;

    int nC = K / KC;
    issue_stage(0); CP_COMMIT();
    issue_stage(1); CP_COMMIT();

    int arow0 = wm * 32 + (lane & 15);
    int axr   = arow0 & 7;
    int acs   = lane >> 4;
    int brow0 = wn * 32 + (lane & 7) + ((lane >> 4) << 3);
    int bxr   = brow0 & 7;
    int bcs   = (lane >> 3) & 1;

    for (int ch = 0; ch < nC; ch++) {
        CP_WAIT1();
        __syncthreads();
        if (ch + 2 < nC) issue_stage(ch + 2);
        CP_COMMIT();

        uint32_t base16 = smb + (uint32_t)(ch % GSTAGES) * GSTAGE_BYTES;
        #pragma unroll
        for (int s = 0; s < 4; s++) {
            uint32_t ah[2][4], al[2][4], bh[2][4], bl[2][4];
            #pragma unroll
            for (int mt = 0; mt < 2; mt++) {
                uint32_t off = (uint32_t)((arow0 + mt * 16) * 8 + ((2 * s + acs) ^ axr)) * 16;
                ldm4(ah[mt], base16 + off);
                ldm4(al[mt], base16 + 16384 + off);
            }
            #pragma unroll
            for (int ng = 0; ng < 2; ng++) {
                uint32_t off = (uint32_t)((brow0 + ng * 16) * 8 + ((2 * s + bcs) ^ bxr)) * 16;
                ldm4(bh[ng], base16 + 32768 + off);
                ldm4(bl[ng], base16 + 49152 + off);
            }
            // product-major: all 8 independent tiles per product, dependent MMAs 8 apart
            #pragma unroll
            for (int p = 0; p < 3; p++)
                #pragma unroll
                for (int mt = 0; mt < 2; mt++)
                    #pragma unroll
                    for (int ng = 0; ng < 2; ng++)
                        #pragma unroll
                        for (int hf = 0; hf < 2; hf++) {
                            const uint32_t* A = (p == 1) ? al[mt] : ah[mt];
                            const uint32_t* B = (p == 2) ? &bl[ng][hf * 2] : &bh[ng][hf * 2];
                            mma16816(acc[mt][ng * 2 + hf], A, B);
                        }
        }
    }

    bool doRope = (posp != nullptr) && (z < 2);
    int erow = mBase + wm * 32 + (lane >> 2);
    int ecol = nBase + wn * 32 + (lane & 3) * 2;
    #pragma unroll
    for (int mt = 0; mt < 2; mt++)
        #pragma unroll
        for (int n8 = 0; n8 < 4; n8++) {
            int row = erow + mt * 16;
            int col = ecol + n8 * 8;
            float2 v0 = {acc[mt][n8][0], acc[mt][n8][1]};
            float2 v1 = {acc[mt][n8][2], acc[mt][n8][3]};
            if (EPI) {
                float2 r0 = *(const float2*)(R + (size_t)row * N + col);
                float2 r1 = *(const float2*)(R + (size_t)(row + 8) * N + col);
                v0.x += r0.x; v0.y += r0.y; v1.x += r1.x; v1.y += r1.y;
            }
            if (doRope) {
                int kk = (col & 63) >> 1;
                float f = exp2f((float)kk * -0.41524101186092029f);
                float p0 = (float)posp[row & (SS - 1)];
                float p1 = (float)posp[(row + 8) & (SS - 1)];
                float s0, c0, s1, c1;
                sincosf(p0 * f, &s0, &c0);
                sincosf(p1 * f, &s1, &c1);
                float e = v0.x, o = v0.y;
                v0.x = e * c0 - o * s0; v0.y = e * s0 + o * c0;
                e = v1.x; o = v1.y;
                v1.x = e * c1 - o * s1; v1.y = e * s1 + o * c1;
            }
            *(float2*)(C + (size_t)row * N + col) = v0;
            *(float2*)(C + (size_t)(row + 8) * N + col) = v1;
        }
}

// ================= RMSNorm -> bf16 hi/lo =================
__global__ __launch_bounds__(256) void rmsnorm_split_kernel(const float* __restrict__ x,
                                                            const float* __restrict__ w,
                                                            __nv_bfloat16* __restrict__ oh,
                                                            __nv_bfloat16* __restrict__ ol) {
    int row = blockIdx.x;
    const float4* xr = (const float4*)(x + (size_t)row * DM);
    float4 v = xr[threadIdx.x];
    float ss = v.x*v.x + v.y*v.y + v.z*v.z + v.w*v.w;
    #pragma unroll
    for (int off = 16; off; off >>= 1) ss += __shfl_xor_sync(0xFFFFFFFFu, ss, off);
    __shared__ float sred[8];
    int lane = threadIdx.x & 31, wid = threadIdx.x >> 5;
    if (lane == 0) sred[wid] = ss;
    __syncthreads();
    if (wid == 0) {
        float t = (lane < 8) ? sred[lane] : 0.0f;
        #pragma unroll
        for (int off = 4; off; off >>= 1) t += __shfl_xor_sync(0xFFFFFFFFu, t, off);
        if (lane == 0) sred[0] = t;
    }
    __syncthreads();
    float r = rsqrtf(sred[0] * (1.0f / DM) + 1e-5f);
    float4 wv = ((const float4*)w)[threadIdx.x];
    float4 o = {v.x*wv.x*r, v.y*wv.y*r, v.z*wv.z*r, v.w*wv.w*r};
    __nv_bfloat16 hx, lx, hy, ly, hz, lz, hw, lw;
    split1(o.x, hx, lx); split1(o.y, hy, ly);
    split1(o.z, hz, lz); split1(o.w, hw, lw);
    ((uint2*)(oh + (size_t)row * DM))[threadIdx.x] = make_uint2(pk2(hx, hy), pk2(hz, hw));
    ((uint2*)(ol + (size_t)row * DM))[threadIdx.x] = make_uint2(pk2(lx, ly), pk2(lz, lw));
}

// ================= MMA flash attention =================
__global__ __launch_bounds__(128) void attn_mma(const float* __restrict__ Q,
                                                const float* __restrict__ K,
                                                const float* __restrict__ V,
                                                __nv_bfloat16* __restrict__ Oh,
                                                __nv_bfloat16* __restrict__ Ol) {
    __shared__ uint4 sQh[512], sQl[512], sKh[512], sKl[512], sVh[512], sVl[512];
    int tid = threadIdx.x, lane = tid & 31, wm = tid >> 5;
    int g = lane >> 2, tig = lane & 3;
    int b = blockIdx.y >> 4, h = blockIdx.y & 15;
    int qBase = blockIdx.x * 64;

    uint32_t aQh = smem_u32(sQh), aQl = smem_u32(sQl);
    uint32_t aKh = smem_u32(sKh), aKl = smem_u32(sKl);
    uint32_t aVh = smem_u32(sVh), aVl = smem_u32(sVl);

    auto load_tile = [&](const float* src, uint4* dh, uint4* dl) {
        #pragma unroll
        for (int i = 0; i < 4; i++) {
            int c = tid + i * 128;
            int r = c >> 3, ch = c & 7;
            const float4* p = (const float4*)(src + (size_t)r * (NH * DKH) + ch * 8);
            float4 u = p[0], v = p[1];
            uint4 hi, lo;
            cvt8(u, v, hi, lo);
            int s = r * 8 + (ch ^ (r & 7));
            dh[s] = hi; dl[s] = lo;
        }
    };

    load_tile(Q + ((size_t)(b * SS + qBase) * NH + h) * DKH, sQh, sQl);
    __syncthreads();

    uint32_t qh[4][4], ql[4][4];
    {
        int row = wm * 16 + (lane & 15);
        int cs  = lane >> 4;
        #pragma unroll
        for (int ks = 0; ks < 4; ks++) {
            uint32_t off = (uint32_t)(row * 8 + ((ks * 2 + cs) ^ (row & 7))) * 16;
            ldm4(qh[ks], aQh + off);
            ldm4(ql[ks], aQl + off);
        }
    }

    float o[8][4];
    #pragma unroll
    for (int t = 0; t < 8; t++)
        #pragma unroll
        for (int j = 0; j < 4; j++) o[t][j] = 0.0f;
    float m0 = -1e30f, m1 = -1e30f, l0 = 0.0f, l1 = 0.0f;

    int krow = (lane & 7) + ((lane >> 4) << 3);
    int kcs  = (lane >> 3) & 1;
    int vrow = lane & 15;
    int vcs  = lane >> 4;

    const float sc = 0.125f * 1.44269504f;

    for (int kv0 = 0; kv0 <= qBase; kv0 += 64) {
        __syncthreads();
        load_tile(K + ((size_t)(b * SS + kv0) * NH + h) * DKH, sKh, sKl);
        load_tile(V + ((size_t)(b * SS + kv0) * NH + h) * DKH, sVh, sVl);
        __syncthreads();

        float s[8][4];
        #pragma unroll
        for (int t = 0; t < 8; t++)
            #pragma unroll
            for (int j = 0; j < 4; j++) s[t][j] = 0.0f;
        #pragma unroll
        for (int ks = 0; ks < 4; ks++) {
            #pragma unroll
            for (int g2 = 0; g2 < 4; g2++) {
                int row = g2 * 16 + krow;
                uint32_t off = (uint32_t)(row * 8 + ((ks * 2 + kcs) ^ (row & 7))) * 16;
                uint32_t kb[4], kl[4];
                ldm4(kb, aKh + off);
                ldm4(kl, aKl + off);
                // product-major: dependent MMAs 2 apart
                #pragma unroll
                for (int p = 0; p < 3; p++)
                    #pragma unroll
                    for (int hf = 0; hf < 2; hf++) {
                        const uint32_t* A = (p == 1) ? ql[ks] : qh[ks];
                        const uint32_t* B = (p == 2) ? &kl[hf * 2] : &kb[hf * 2];
                        mma16816(s[g2 * 2 + hf], A, B);
                    }
            }
        }

        if (kv0 == qBase) {
            #pragma unroll
            for (int t = 0; t < 8; t++)
                #pragma unroll
                for (int j = 0; j < 4; j++) {
                    int Lc = 8 * t + 2 * tig + (j & 1);
                    int Lr = wm * 16 + g + ((j >> 1) << 3);
                    s[t][j] = (Lc <= Lr) ? s[t][j] * sc : -1e30f;
                }
        } else {
            #pragma unroll
            for (int t = 0; t < 8; t++)
                #pragma unroll
                for (int j = 0; j < 4; j++) s[t][j] *= sc;
        }

        float rm0 = -1e30f, rm1 = -1e30f;
        #pragma unroll
        for (int t = 0; t < 8; t++) {
            rm0 = fmaxf(rm0, fmaxf(s[t][0], s[t][1]));
            rm1 = fmaxf(rm1, fmaxf(s[t][2], s[t][3]));
        }
        rm0 = fmaxf(rm0, __shfl_xor_sync(0xFFFFFFFFu, rm0, 1));
        rm0 = fmaxf(rm0, __shfl_xor_sync(0xFFFFFFFFu, rm0, 2));
        rm1 = fmaxf(rm1, __shfl_xor_sync(0xFFFFFFFFu, rm1, 1));
        rm1 = fmaxf(rm1, __shfl_xor_sync(0xFFFFFFFFu, rm1, 2));
        float nm0 = fmaxf(m0, rm0), nm1 = fmaxf(m1, rm1);
        float c0 = exp2f(m0 - nm0), c1 = exp2f(m1 - nm1);
        m0 = nm0; m1 = nm1;
        float rs0 = 0.0f, rs1 = 0.0f;
        #pragma unroll
        for (int t = 0; t < 8; t++) {
            s[t][0] = exp2f(s[t][0] - nm0);
            s[t][1] = exp2f(s[t][1] - nm0);
            s[t][2] = exp2f(s[t][2] - nm1);
            s[t][3] = exp2f(s[t][3] - nm1);
            rs0 += s[t][0] + s[t][1];
            rs1 += s[t][2] + s[t][3];
        }
        l0 = l0 * c0 + rs0;
        l1 = l1 * c1 + rs1;
        #pragma unroll
        for (int t = 0; t < 8; t++) {
            o[t][0] *= c0; o[t][1] *= c0;
            o[t][2] *= c1; o[t][3] *= c1;
        }

        #pragma unroll
        for (int ks = 0; ks < 4; ks++) {
            uint32_t pah[4], pal[4];
            #pragma unroll
            for (int half = 0; half < 2; half++) {
                const float* ps = s[2 * ks + half];
                __nv_bfloat16 h0, lo0, h1, lo1, h2, lo2, h3, lo3;
                split1(ps[0], h0, lo0); split1(ps[1], h1, lo1);
                split1(ps[2], h2, lo2); split1(ps[3], h3, lo3);
                pah[half * 2 + 0] = pk2(h0, h1);  pal[half * 2 + 0] = pk2(lo0, lo1);
                pah[half * 2 + 1] = pk2(h2, h3);  pal[half * 2 + 1] = pk2(lo2, lo3);
            }
            #pragma unroll
            for (int g2 = 0; g2 < 4; g2++) {
                int row = ks * 16 + vrow;
                uint32_t off = (uint32_t)(row * 8 + ((g2 * 2 + vcs) ^ (row & 7))) * 16;
                uint32_t vb[4], vl[4];
                ldm4t(vb, aVh + off);
                ldm4t(vl, aVl + off);
                // product-major
                #pragma unroll
                for (int p = 0; p < 3; p++)
                    #pragma unroll
                    for (int hf = 0; hf < 2; hf++) {
                        const uint32_t* A = (p == 1) ? pal : pah;
                        const uint32_t* B = (p == 2) ? &vl[hf * 2] : &vb[hf * 2];
                        mma16816(o[g2 * 2 + hf], A, B);
                    }
            }
        }
    }

    l0 += __shfl_xor_sync(0xFFFFFFFFu, l0, 1);
    l0 += __shfl_xor_sync(0xFFFFFFFFu, l0, 2);
    l1 += __shfl_xor_sync(0xFFFFFFFFu, l1, 1);
    l1 += __shfl_xor_sync(0xFFFFFFFFu, l1, 2);
    float inv0 = 1.0f / l0, inv1 = 1.0f / l1;

    int r0 = qBase + wm * 16 + g;
    int r1 = r0 + 8;
    size_t o0 = ((size_t)(b * SS + r0) * NH + h) * DKH;
    size_t o1 = ((size_t)(b * SS + r1) * NH + h) * DKH;
    #pragma unroll
    for (int t = 0; t < 8; t++) {
        int d = 8 * t + 2 * tig;
        float v0 = o[t][0] * inv0, v1 = o[t][1] * inv0;
        float v2 = o[t][2] * inv1, v3 = o[t][3] * inv1;
        __nv_bfloat16 h0, lo0, h1, lo1, h2, lo2, h3, lo3;
        split1(v0, h0, lo0); split1(v1, h1, lo1);
        split1(v2, h2, lo2); split1(v3, h3, lo3);
        *(uint32_t*)(Oh + o0 + d) = pk2(h0, h1);
        *(uint32_t*)(Ol + o0 + d) = pk2(lo0, lo1);
        *(uint32_t*)(Oh + o1 + d) = pk2(h2, h3);
        *(uint32_t*)(Ol + o1 + d) = pk2(lo2, lo3);
    }
}

// ================= SwiGLU -> bf16 hi/lo =================
__global__ __launch_bounds__(256) void silu_split_kernel(const float4* __restrict__ g,
                                                         const float4* __restrict__ u,
                                                         uint2* __restrict__ oh,
                                                         uint2* __restrict__ ol, int n4) {
    int i = blockIdx.x * 256 + threadIdx.x;
    if (i >= n4) return;
    float4 a = g[i], bb = u[i];
    a.x = a.x / (1.0f + __expf(-a.x)) * bb.x;
    a.y = a.y / (1.0f + __expf(-a.y)) * bb.y;
    a.z = a.z / (1.0f + __expf(-a.z)) * bb.z;
    a.w = a.w / (1.0f + __expf(-a.w)) * bb.w;
    __nv_bfloat16 hx, lx, hy, ly, hz, lz, hw, lw;
    split1(a.x, hx, lx); split1(a.y, hy, ly);
    split1(a.z, hz, lz); split1(a.w, hw, lw);
    oh[i] = make_uint2(pk2(hx, hy), pk2(hz, hw));
    ol[i] = make_uint2(pk2(lx, ly), pk2(lz, lw));
}

extern "C" void kernel_launch(void* const* d_in, const int* in_sizes, int n_in,
                              void* d_out, int out_size) {
    const float* x   = (const float*)d_in[0];
    const float* ln1 = (const float*)d_in[1];
    const float* qw  = (const float*)d_in[2];
    const float* kw  = (const float*)d_in[3];
    const float* vw  = (const float*)d_in[4];
    const float* ow  = (const float*)d_in[5];
    const float* ln2 = (const float*)d_in[6];
    const float* w1  = (const float*)d_in[7];
    const float* w3  = (const float*)d_in[8];
    const float* w2  = (const float*)d_in[9];
    const int*   pos = (const int*)d_in[10];
    float* out = (float*)d_out;

    float *q, *k, *v, *x1, *gt, *up;
    cudaGetSymbolAddress((void**)&q,  g_q);
    cudaGetSymbolAddress((void**)&k,  g_k);
    cudaGetSymbolAddress((void**)&v,  g_v);
    cudaGetSymbolAddress((void**)&x1, g_x1);
    cudaGetSymbolAddress((void**)&gt, g_gt);
    cudaGetSymbolAddress((void**)&up, g_up);
    __nv_bfloat16 *hh, *hl, *cxh, *cxl, *glh, *gll;
    __nv_bfloat16 *wqh, *wql, *wkh, *wkl, *wvh, *wvl, *woh, *wol;
    __nv_bfloat16 *w1h, *w1l, *w3h, *w3l, *w2h, *w2l;
    cudaGetSymbolAddress((void**)&hh,  g_h_h);  cudaGetSymbolAddress((void**)&hl,  g_h_l);
    cudaGetSymbolAddress((void**)&cxh, g_cx_h); cudaGetSymbolAddress((void**)&cxl, g_cx_l);
    cudaGetSymbolAddress((void**)&glh, g_gl_h); cudaGetSymbolAddress((void**)&gll, g_gl_l);
    cudaGetSymbolAddress((void**)&wqh, g_wq_h); cudaGetSymbolAddress((void**)&wql, g_wq_l);
    cudaGetSymbolAddress((void**)&wkh, g_wk_h); cudaGetSymbolAddress((void**)&wkl, g_wk_l);
    cudaGetSymbolAddress((void**)&wvh, g_wv_h); cudaGetSymbolAddress((void**)&wvl, g_wv_l);
    cudaGetSymbolAddress((void**)&woh, g_wo_h); cudaGetSymbolAddress((void**)&wol, g_wo_l);
    cudaGetSymbolAddress((void**)&w1h, g_w1_h); cudaGetSymbolAddress((void**)&w1l, g_w1_l);
    cudaGetSymbolAddress((void**)&w3h, g_w3_h); cudaGetSymbolAddress((void**)&w3l, g_w3_l);
    cudaGetSymbolAddress((void**)&w2h, g_w2_h); cudaGetSymbolAddress((void**)&w2l, g_w2_l);

    cudaFuncSetAttribute(mma_gemm<0>, cudaFuncAttributeMaxDynamicSharedMemorySize, GSMEM);
    cudaFuncSetAttribute(mma_gemm<1>, cudaFuncAttributeMaxDynamicSharedMemorySize, GSMEM);

    const int n4_mm = DM * DM / 4, n4_ff = DFF * DM / 4;
    split4_kernel<<<dim3((n4_mm + 1023) / 1024, 4), 256>>>(
        (const float4*)qw, (const float4*)kw, (const float4*)vw, (const float4*)ow,
        (uint2*)wqh, (uint2*)wql, (uint2*)wkh, (uint2*)wkl,
        (uint2*)wvh, (uint2*)wvl, (uint2*)woh, (uint2*)wol, n4_mm);
    split3_kernel<<<dim3((n4_ff + 1023) / 1024, 3), 256>>>(
        (const float4*)w1, (const float4*)w3, (const float4*)w2,
        (uint2*)w1h, (uint2*)w1l, (uint2*)w3h, (uint2*)w3l, (uint2*)w2h, (uint2*)w2l, n4_ff);

    dim3 gqkv(DM / 128, ROWS / 128, 3);   // (8, 32, 3)
    dim3 gq1 (DM / 128, ROWS / 128, 1);   // (8, 32)
    dim3 gf2 (DFF / 128, ROWS / 128, 2);  // (21, 32, 2)
    dim3 ga  (SS / 64, BB * NH);          // (32, 32)

    rmsnorm_split_kernel<<<ROWS, 256>>>(x, ln1, hh, hl);
    mma_gemm<0><<<gqkv, 512, GSMEM>>>(hh, hl, wqh, wql, wkh, wkl, wvh, wvl,
                                      nullptr, pos, q, k, v, ROWS, DM, DM);
    attn_mma<<<ga, 128>>>(q, k, v, cxh, cxl);
    mma_gemm<1><<<gq1, 512, GSMEM>>>(cxh, cxl, woh, wol, nullptr, nullptr, nullptr, nullptr,
                                     x, nullptr, x1, nullptr, nullptr, ROWS, DM, DM);
    rmsnorm_split_kernel<<<ROWS, 256>>>(x1, ln2, hh, hl);
    mma_gemm<0><<<gf2, 512, GSMEM>>>(hh, hl, w1h, w1l, w3h, w3l, nullptr, nullptr,
                                     nullptr, nullptr, gt, up, nullptr, ROWS, DFF, DM);
    silu_split_kernel<<<(ROWS * DFF / 4 + 255) / 256, 256>>>((const float4*)gt, (const float4*)up,
                                                             (uint2*)glh, (uint2*)gll, ROWS * DFF / 4);
    mma_gemm<1><<<gq1, 512, GSMEM>>>(glh, gll, w2h, w2l, nullptr, nullptr, nullptr, nullptr,
                                     x1, nullptr, out, nullptr, nullptr, ROWS, DM, DFF);
}

// round 15
// speedup vs baseline: 1.0525x; 1.0525x over previous
#include <cuda_runtime.h>
#include <cuda_bf16.h>
#include <cstdint>
#include <math.h>

#define BB 2
#define SS 2048
#define DM 1024
#define NH 16
#define DKH 64
#define DFF 2688
#define ROWS (BB*SS)   // 4096

// ---- fp32 scratch ----
__device__ float g_x1 [ROWS*DM];
__device__ float g_gt [ROWS*DFF];
__device__ float g_up [ROWS*DFF];
// ---- bf16 split scratch (hi/lo) ----
__device__ __nv_bfloat16 g_qh [ROWS*DM], g_ql [ROWS*DM];
__device__ __nv_bfloat16 g_kh [ROWS*DM], g_kl [ROWS*DM];
__device__ __nv_bfloat16 g_vh [ROWS*DM], g_vl [ROWS*DM];
__device__ __nv_bfloat16 g_h_h [ROWS*DM],  g_h_l [ROWS*DM];
__device__ __nv_bfloat16 g_cx_h[ROWS*DM],  g_cx_l[ROWS*DM];
__device__ __nv_bfloat16 g_gl_h[ROWS*DFF], g_gl_l[ROWS*DFF];
__device__ __nv_bfloat16 g_wq_h[DM*DM],  g_wq_l[DM*DM];
__device__ __nv_bfloat16 g_wk_h[DM*DM],  g_wk_l[DM*DM];
__device__ __nv_bfloat16 g_wv_h[DM*DM],  g_wv_l[DM*DM];
__device__ __nv_bfloat16 g_wo_h[DM*DM],  g_wo_l[DM*DM];
__device__ __nv_bfloat16 g_w1_h[DFF*DM], g_w1_l[DFF*DM];
__device__ __nv_bfloat16 g_w3_h[DFF*DM], g_w3_l[DFF*DM];
__device__ __nv_bfloat16 g_w2_h[DM*DFF], g_w2_l[DM*DFF];

// ================= helpers =================
__device__ __forceinline__ uint32_t smem_u32(const void* p) {
    uint32_t a;
    asm("{ .reg .u64 t; cvta.to.shared.u64 t, %1; cvt.u32.u64 %0, t; }" : "=r"(a) : "l"(p));
    return a;
}
__device__ __forceinline__ uint32_t pk2(__nv_bfloat16 a, __nv_bfloat16 b) {
    return (uint32_t)__bfloat16_as_ushort(a) | ((uint32_t)__bfloat16_as_ushort(b) << 16);
}
__device__ __forceinline__ void split1(float x, __nv_bfloat16& h, __nv_bfloat16& l) {
    h = __float2bfloat16(x);
    l = __float2bfloat16(x - __bfloat162float(h));
}
__device__ __forceinline__ void ldm4(uint32_t* r, uint32_t addr) {
    asm volatile("ldmatrix.sync.aligned.m8n8.x4.shared.b16 {%0,%1,%2,%3}, [%4];"
        : "=r"(r[0]), "=r"(r[1]), "=r"(r[2]), "=r"(r[3]) : "r"(addr));
}
__device__ __forceinline__ void ldm4t(uint32_t* r, uint32_t addr) {
    asm volatile("ldmatrix.sync.aligned.m8n8.x4.trans.shared.b16 {%0,%1,%2,%3}, [%4];"
        : "=r"(r[0]), "=r"(r[1]), "=r"(r[2]), "=r"(r[3]) : "r"(addr));
}
__device__ __forceinline__ void mma16816(float* d, const uint32_t* a, const uint32_t* b) {
    asm volatile("mma.sync.aligned.m16n8k16.row.col.f32.bf16.bf16.f32 "
        "{%0,%1,%2,%3},{%4,%5,%6,%7},{%8,%9},{%0,%1,%2,%3};"
        : "+f"(d[0]), "+f"(d[1]), "+f"(d[2]), "+f"(d[3])
        : "r"(a[0]), "r"(a[1]), "r"(a[2]), "r"(a[3]), "r"(b[0]), "r"(b[1]));
}
__device__ __forceinline__ void cpasync16(uint32_t saddr, const void* gaddr) {
    asm volatile("cp.async.cg.shared.global [%0], [%1], 16;" :: "r"(saddr), "l"(gaddr));
}
#define CP_COMMIT()   asm volatile("cp.async.commit_group;" ::: "memory")
#define CP_WAIT1()    asm volatile("cp.async.wait_group 1;" ::: "memory")
#define CP_WAIT_ALL() asm volatile("cp.async.wait_all;" ::: "memory")

// ================= merged split kernels: fp32 -> bf16 hi/lo (MLP=4) =================
__device__ __forceinline__ void split_body(const float4* in, uint2* hi, uint2* lo, int i) {
    float4 v = in[i];
    __nv_bfloat16 hx, lx, hy, ly, hz, lz, hw, lw;
    split1(v.x, hx, lx); split1(v.y, hy, ly);
    split1(v.z, hz, lz); split1(v.w, hw, lw);
    hi[i] = make_uint2(pk2(hx, hy), pk2(hz, hw));
    lo[i] = make_uint2(pk2(lx, ly), pk2(lz, lw));
}
__global__ __launch_bounds__(256) void split4_kernel(
    const float4* a, const float4* b, const float4* c, const float4* d,
    uint2* ah, uint2* al, uint2* bh, uint2* bl,
    uint2* ch, uint2* cl, uint2* dh, uint2* dl, int n4) {
    int base = blockIdx.x * 1024 + threadIdx.x;
    int w = blockIdx.y;
    const float4* in = (w == 0) ? a : (w == 1) ? b : (w == 2) ? c : d;
    uint2* hi = (w == 0) ? ah : (w == 1) ? bh : (w == 2) ? ch : dh;
    uint2* lo = (w == 0) ? al : (w == 1) ? bl : (w == 2) ? cl : dl;
    #pragma unroll
    for (int it = 0; it < 4; it++) {
        int i = base + it * 256;
        if (i < n4) split_body(in, hi, lo, i);
    }
}
__global__ __launch_bounds__(256) void split3_kernel(
    const float4* a, const float4* b, const float4* c,
    uint2* ah, uint2* al, uint2* bh, uint2* bl, uint2* ch, uint2* cl, int n4) {
    int base = blockIdx.x * 1024 + threadIdx.x;
    int w = blockIdx.y;
    const float4* in = (w == 0) ? a : (w == 1) ? b : c;
    uint2* hi = (w == 0) ? ah : (w == 1) ? bh : ch;
    uint2* lo = (w == 0) ? al : (w == 1) ? bl : cl;
    #pragma unroll
    for (int it = 0; it < 4; it++) {
        int i = base + it * 256;
        if (i < n4) split_body(in, hi, lo, i);
    }
}

// ================= GEMM mainloop (shared by both GEMM kernels) =================
#define KC 64
#define GSTAGES 3
#define GSTAGE_BYTES 65536
#define GSMEM (GSTAGES*GSTAGE_BYTES) // 196608

#define GEMM_MAINLOOP(pAh, pAl, pBh, pBl, K)                                           \
    int lr = tid >> 2, lc = tid & 3;                                                   \
    int xr8 = lr & 7;                                                                  \
    uint32_t rbase = smb + (uint32_t)lr * 128;                                         \
    auto issue_stage = [&](int st) {                                                   \
        int k0 = st * KC;                                                              \
        uint32_t d = rbase + (uint32_t)(st % GSTAGES) * GSTAGE_BYTES;                  \
        _Pragma("unroll")                                                              \
        for (int c = 0; c < 2; c++) {                                                  \
            int chh = lc + c * 4;                                                      \
            uint32_t so = (uint32_t)(chh ^ xr8) * 16;                                  \
            cpasync16(d + so,         pAh + k0 + chh * 8);                             \
            cpasync16(d + 16384 + so, pAl + k0 + chh * 8);                             \
            cpasync16(d + 32768 + so, pBh + k0 + chh * 8);                             \
            cpasync16(d + 49152 + so, pBl + k0 + chh * 8);                             \
        }                                                                              \
    };                                                                                 \
    float acc[2][4][4];                                                                \
    _Pragma("unroll")                                                                  \
    for (int a = 0; a < 2; a++)                                                        \
        _Pragma("unroll")                                                              \
        for (int b2 = 0; b2 < 4; b2++)                                                 \
            _Pragma("unroll")                                                          \
            for (int c = 0; c < 4; c++) acc[a][b2][c] = 0.0f;                          \
    int nC = (K) / KC;                                                                 \
    issue_stage(0); CP_COMMIT();                                                       \
    issue_stage(1); CP_COMMIT();                                                       \
    int arow0 = wm * 32 + (lane & 15);                                                 \
    int axr   = arow0 & 7;                                                             \
    int acs   = lane >> 4;                                                             \
    int brow0 = wn * 32 + (lane & 7) + ((lane >> 4) << 3);                             \
    int bxr   = brow0 & 7;                                                             \
    int bcs   = (lane >> 3) & 1;                                                       \
    for (int ch = 0; ch < nC; ch++) {                                                  \
        CP_WAIT1();                                                                    \
        __syncthreads();                                                               \
        if (ch + 2 < nC) issue_stage(ch + 2);                                          \
        CP_COMMIT();                                                                   \
        uint32_t base16 = smb + (uint32_t)(ch % GSTAGES) * GSTAGE_BYTES;               \
        _Pragma("unroll")                                                              \
        for (int s = 0; s < 4; s++) {                                                  \
            uint32_t ah[2][4], al[2][4], bh[2][4], bl[2][4];                           \
            _Pragma("unroll")                                                          \
            for (int mt = 0; mt < 2; mt++) {                                           \
                uint32_t off = (uint32_t)((arow0 + mt * 16) * 8 + ((2 * s + acs) ^ axr)) * 16; \
                ldm4(ah[mt], base16 + off);                                            \
                ldm4(al[mt], base16 + 16384 + off);                                    \
            }                                                                          \
            _Pragma("unroll")                                                          \
            for (int ng = 0; ng < 2; ng++) {                                           \
                uint32_t off = (uint32_t)((brow0 + ng * 16) * 8 + ((2 * s + bcs) ^ bxr)) * 16; \
                ldm4(bh[ng], base16 + 32768 + off);                                    \
                ldm4(bl[ng], base16 + 49152 + off);                                    \
            }                                                                          \
            _Pragma("unroll")                                                          \
            for (int p = 0; p < 3; p++)                                                \
                _Pragma("unroll")                                                      \
                for (int mt = 0; mt < 2; mt++)                                         \
                    _Pragma("unroll")                                                  \
                    for (int ng = 0; ng < 2; ng++)                                     \
                        _Pragma("unroll")                                              \
                        for (int hf = 0; hf < 2; hf++) {                               \
                            const uint32_t* A = (p == 1) ? al[mt] : ah[mt];            \
                            const uint32_t* B = (p == 2) ? &bl[ng][hf * 2] : &bh[ng][hf * 2]; \
                            mma16816(acc[mt][ng * 2 + hf], A, B);                      \
                        }                                                              \
        }                                                                              \
    }

// ================= generic MMA GEMM: fp32 out (+residual) =================
template<int EPI>
__global__ __launch_bounds__(512, 1) void mma_gemm(
    const __nv_bfloat16* __restrict__ Ah, const __nv_bfloat16* __restrict__ Al,
    const __nv_bfloat16* __restrict__ Bh0, const __nv_bfloat16* __restrict__ Bl0,
    const __nv_bfloat16* __restrict__ Bh1, const __nv_bfloat16* __restrict__ Bl1,
    const float* __restrict__ R,
    float* __restrict__ C0, float* __restrict__ C1,
    int M, int N, int K)
{
    extern __shared__ uint4 sm4[];
    uint32_t smb = smem_u32(sm4);
    int tid = threadIdx.x, lane = tid & 31, wid = tid >> 5;
    int wm = wid & 3, wn = wid >> 2;
    int mBase = blockIdx.y * 128, nBase = blockIdx.x * 128;
    int z = blockIdx.z;
    const __nv_bfloat16* Bh = (z == 0) ? Bh0 : Bh1;
    const __nv_bfloat16* Bl = (z == 0) ? Bl0 : Bl1;
    float* C = (z == 0) ? C0 : C1;

    const __nv_bfloat16* pAh = Ah + (size_t)(mBase + (tid >> 2)) * K;
    const __nv_bfloat16* pAl = Al + (size_t)(mBase + (tid >> 2)) * K;
    const __nv_bfloat16* pBh = Bh + (size_t)(nBase + (tid >> 2)) * K;
    const __nv_bfloat16* pBl = Bl + (size_t)(nBase + (tid >> 2)) * K;

    GEMM_MAINLOOP(pAh, pAl, pBh, pBl, K)

    int erow = mBase + wm * 32 + (lane >> 2);
    int ecol = nBase + wn * 32 + (lane & 3) * 2;
    #pragma unroll
    for (int mt = 0; mt < 2; mt++)
        #pragma unroll
        for (int n8 = 0; n8 < 4; n8++) {
            int row = erow + mt * 16;
            int col = ecol + n8 * 8;
            float2 v0 = {acc[mt][n8][0], acc[mt][n8][1]};
            float2 v1 = {acc[mt][n8][2], acc[mt][n8][3]};
            if (EPI) {
                float2 r0 = *(const float2*)(R + (size_t)row * N + col);
                float2 r1 = *(const float2*)(R + (size_t)(row + 8) * N + col);
                v0.x += r0.x; v0.y += r0.y; v1.x += r1.x; v1.y += r1.y;
            }
            *(float2*)(C + (size_t)row * N + col) = v0;
            *(float2*)(C + (size_t)(row + 8) * N + col) = v1;
        }
}

// ================= QKV GEMM: fused RoPE (z<2) + split bf16 hi/lo output =================
__global__ __launch_bounds__(512, 1) void mma_gemm_qkv(
    const __nv_bfloat16* __restrict__ Ah, const __nv_bfloat16* __restrict__ Al,
    const __nv_bfloat16* __restrict__ Bh0, const __nv_bfloat16* __restrict__ Bl0,
    const __nv_bfloat16* __restrict__ Bh1, const __nv_bfloat16* __restrict__ Bl1,
    const __nv_bfloat16* __restrict__ Bh2, const __nv_bfloat16* __restrict__ Bl2,
    const int* __restrict__ posp,
    __nv_bfloat16* __restrict__ Ch0, __nv_bfloat16* __restrict__ Cl0,
    __nv_bfloat16* __restrict__ Ch1, __nv_bfloat16* __restrict__ Cl1,
    __nv_bfloat16* __restrict__ Ch2, __nv_bfloat16* __restrict__ Cl2,
    int M, int N, int K)
{
    extern __shared__ uint4 sm4[];
    uint32_t smb = smem_u32(sm4);
    int tid = threadIdx.x, lane = tid & 31, wid = tid >> 5;
    int wm = wid & 3, wn = wid >> 2;
    int mBase = blockIdx.y * 128, nBase = blockIdx.x * 128;
    int z = blockIdx.z;
    const __nv_bfloat16* Bh = (z == 0) ? Bh0 : (z == 1) ? Bh1 : Bh2;
    const __nv_bfloat16* Bl = (z == 0) ? Bl0 : (z == 1) ? Bl1 : Bl2;
    __nv_bfloat16* Ch = (z == 0) ? Ch0 : (z == 1) ? Ch1 : Ch2;
    __nv_bfloat16* Cl = (z == 0) ? Cl0 : (z == 1) ? Cl1 : Cl2;

    const __nv_bfloat16* pAh = Ah + (size_t)(mBase + (tid >> 2)) * K;
    const __nv_bfloat16* pAl = Al + (size_t)(mBase + (tid >> 2)) * K;
    const __nv_bfloat16* pBh = Bh + (size_t)(nBase + (tid >> 2)) * K;
    const __nv_bfloat16* pBl = Bl + (size_t)(nBase + (tid >> 2)) * K;

    GEMM_MAINLOOP(pAh, pAl, pBh, pBl, K)

    bool doRope = (z < 2);
    int erow = mBase + wm * 32 + (lane >> 2);
    int ecol = nBase + wn * 32 + (lane & 3) * 2;
    #pragma unroll
    for (int mt = 0; mt < 2; mt++)
        #pragma unroll
        for (int n8 = 0; n8 < 4; n8++) {
            int row = erow + mt * 16;
            int col = ecol + n8 * 8;
            float2 v0 = {acc[mt][n8][0], acc[mt][n8][1]};
            float2 v1 = {acc[mt][n8][2], acc[mt][n8][3]};
            if (doRope) {
                int kk = (col & 63) >> 1;
                float f = exp2f((float)kk * -0.41524101186092029f);
                float p0 = (float)posp[row & (SS - 1)];
                float p1 = (float)posp[(row + 8) & (SS - 1)];
                float s0, c0, s1, c1;
                sincosf(p0 * f, &s0, &c0);
                sincosf(p1 * f, &s1, &c1);
                float e = v0.x, o = v0.y;
                v0.x = e * c0 - o * s0; v0.y = e * s0 + o * c0;
                e = v1.x; o = v1.y;
                v1.x = e * c1 - o * s1; v1.y = e * s1 + o * c1;
            }
            __nv_bfloat16 h0, l0, h1, l1, h2, l2, h3, l3;
            split1(v0.x, h0, l0); split1(v0.y, h1, l1);
            split1(v1.x, h2, l2); split1(v1.y, h3, l3);
            *(uint32_t*)(Ch + (size_t)row * N + col)       = pk2(h0, h1);
            *(uint32_t*)(Cl + (size_t)row * N + col)       = pk2(l0, l1);
            *(uint32_t*)(Ch + (size_t)(row + 8) * N + col) = pk2(h2, h3);
            *(uint32_t*)(Cl + (size_t)(row + 8) * N + col) = pk2(l2, l3);
        }
}

// ================= RMSNorm -> bf16 hi/lo =================
__global__ __launch_bounds__(256) void rmsnorm_split_kernel(const float* __restrict__ x,
                                                            const float* __restrict__ w,
                                                            __nv_bfloat16* __restrict__ oh,
                                                            __nv_bfloat16* __restrict__ ol) {
    int row = blockIdx.x;
    const float4* xr = (const float4*)(x + (size_t)row * DM);
    float4 v = xr[threadIdx.x];
    float ss = v.x*v.x + v.y*v.y + v.z*v.z + v.w*v.w;
    #pragma unroll
    for (int off = 16; off; off >>= 1) ss += __shfl_xor_sync(0xFFFFFFFFu, ss, off);
    __shared__ float sred[8];
    int lane = threadIdx.x & 31, wid = threadIdx.x >> 5;
    if (lane == 0) sred[wid] = ss;
    __syncthreads();
    if (wid == 0) {
        float t = (lane < 8) ? sred[lane] : 0.0f;
        #pragma unroll
        for (int off = 4; off; off >>= 1) t += __shfl_xor_sync(0xFFFFFFFFu, t, off);
        if (lane == 0) sred[0] = t;
    }
    __syncthreads();
    float r = rsqrtf(sred[0] * (1.0f / DM) + 1e-5f);
    float4 wv = ((const float4*)w)[threadIdx.x];
    float4 o = {v.x*wv.x*r, v.y*wv.y*r, v.z*wv.z*r, v.w*wv.w*r};
    __nv_bfloat16 hx, lx, hy, ly, hz, lz, hw, lw;
    split1(o.x, hx, lx); split1(o.y, hy, ly);
    split1(o.z, hz, lz); split1(o.w, hw, lw);
    ((uint2*)(oh + (size_t)row * DM))[threadIdx.x] = make_uint2(pk2(hx, hy), pk2(hz, hw));
    ((uint2*)(ol + (size_t)row * DM))[threadIdx.x] = make_uint2(pk2(lx, ly), pk2(lz, lw));
}

// ================= MMA flash attention: 256 thr, 128 q-rows, pre-split bf16 inputs =================
__global__ __launch_bounds__(256) void attn_mma(
    const __nv_bfloat16* __restrict__ Qh, const __nv_bfloat16* __restrict__ Ql,
    const __nv_bfloat16* __restrict__ Kh, const __nv_bfloat16* __restrict__ Kl,
    const __nv_bfloat16* __restrict__ Vh, const __nv_bfloat16* __restrict__ Vl,
    __nv_bfloat16* __restrict__ Oh, __nv_bfloat16* __restrict__ Ol)
{
    extern __shared__ char dsm[];
    uint32_t sb = smem_u32(dsm);
    uint32_t aQh = sb, aQl = sb + 16384;
    uint32_t aKh = sb + 32768, aKl = sb + 40960;
    uint32_t aVh = sb + 49152, aVl = sb + 57344;

    int tid = threadIdx.x, lane = tid & 31, wid = tid >> 5;   // wid 0..7, 16-row slab each
    int g = lane >> 2, tig = lane & 3;
    int b = blockIdx.y >> 4, h = blockIdx.y & 15;
    int qBase = ((int)gridDim.x - 1 - (int)blockIdx.x) * 128;   // heavy tiles first

    // ---- load Q (128 rows, hi+lo) via cp.async ----
    {
        #pragma unroll
        for (int i = 0; i < 4; i++) {
            int c = tid * 4 + i;             // 0..1023
            int r = c >> 3, ch = c & 7;
            size_t go = ((size_t)(b * SS + qBase + r) * NH + h) * DKH + ch * 8;
            uint32_t so = (uint32_t)(r * 8 + (ch ^ (r & 7))) * 16;
            cpasync16(aQh + so, Qh + go);
            cpasync16(aQl + so, Ql + go);
        }
        CP_WAIT_ALL();
    }
    __syncthreads();

    uint32_t qh[4][4], ql[4][4];
    {
        int row = wid * 16 + (lane & 15);
        int cs  = lane >> 4;
        #pragma unroll
        for (int ks = 0; ks < 4; ks++) {
            uint32_t off = (uint32_t)(row * 8 + ((ks * 2 + cs) ^ (row & 7))) * 16;
            ldm4(qh[ks], aQh + off);
            ldm4(ql[ks], aQl + off);
        }
    }

    float o[8][4];
    #pragma unroll
    for (int t = 0; t < 8; t++)
        #pragma unroll
        for (int j = 0; j < 4; j++) o[t][j] = 0.0f;
    float m0 = -1e30f, m1 = -1e30f, l0 = 0.0f, l1 = 0.0f;

    int krow = (lane & 7) + ((lane >> 4) << 3);
    int kcs  = (lane >> 3) & 1;
    int vrow = lane & 15;
    int vcs  = lane >> 4;

    const float sc = 0.125f * 1.44269504f;
    int warpRowMin = qBase + wid * 16;

    for (int kv0 = 0; kv0 < qBase + 128; kv0 += 64) {
        __syncthreads();
        // ---- load K/V tile (64 rows, hi+lo) via cp.async ----
        #pragma unroll
        for (int i = 0; i < 2; i++) {
            int c = tid * 2 + i;             // 0..511
            int r = c >> 3, ch = c & 7;
            size_t go = ((size_t)(b * SS + kv0 + r) * NH + h) * DKH + ch * 8;
            uint32_t so = (uint32_t)(r * 8 + (ch ^ (r & 7))) * 16;
            cpasync16(aKh + so, Kh + go);
            cpasync16(aKl + so, Kl + go);
            cpasync16(aVh + so, Vh + go);
            cpasync16(aVl + so, Vl + go);
        }
        CP_WAIT_ALL();
        __syncthreads();

        if (kv0 <= warpRowMin + 15) {       // warp has at least one unmasked row
            float s[8][4];
            #pragma unroll
            for (int t = 0; t < 8; t++)
                #pragma unroll
                for (int j = 0; j < 4; j++) s[t][j] = 0.0f;
            #pragma unroll
            for (int ks = 0; ks < 4; ks++) {
                #pragma unroll
                for (int g2 = 0; g2 < 4; g2++) {
                    int row = g2 * 16 + krow;
                    uint32_t off = (uint32_t)(row * 8 + ((ks * 2 + kcs) ^ (row & 7))) * 16;
                    uint32_t kb[4], kl2[4];
                    ldm4(kb, aKh + off);
                    ldm4(kl2, aKl + off);
                    #pragma unroll
                    for (int p = 0; p < 3; p++)
                        #pragma unroll
                        for (int hf = 0; hf < 2; hf++) {
                            const uint32_t* A = (p == 1) ? ql[ks] : qh[ks];
                            const uint32_t* B = (p == 2) ? &kl2[hf * 2] : &kb[hf * 2];
                            mma16816(s[g2 * 2 + hf], A, B);
                        }
                }
            }

            if (kv0 + 63 > warpRowMin) {    // diagonal: element mask
                #pragma unroll
                for (int t = 0; t < 8; t++)
                    #pragma unroll
                    for (int j = 0; j < 4; j++) {
                        int Lc = kv0 + 8 * t + 2 * tig + (j & 1);
                        int Lr = warpRowMin + g + ((j >> 1) << 3);
                        s[t][j] = (Lc <= Lr) ? s[t][j] * sc : -1e30f;
                    }
            } else {
                #pragma unroll
                for (int t = 0; t < 8; t++)
                    #pragma unroll
                    for (int j = 0; j < 4; j++) s[t][j] *= sc;
            }

            float rm0 = -1e30f, rm1 = -1e30f;
            #pragma unroll
            for (int t = 0; t < 8; t++) {
                rm0 = fmaxf(rm0, fmaxf(s[t][0], s[t][1]));
                rm1 = fmaxf(rm1, fmaxf(s[t][2], s[t][3]));
            }
            rm0 = fmaxf(rm0, __shfl_xor_sync(0xFFFFFFFFu, rm0, 1));
            rm0 = fmaxf(rm0, __shfl_xor_sync(0xFFFFFFFFu, rm0, 2));
            rm1 = fmaxf(rm1, __shfl_xor_sync(0xFFFFFFFFu, rm1, 1));
            rm1 = fmaxf(rm1, __shfl_xor_sync(0xFFFFFFFFu, rm1, 2));
            float nm0 = fmaxf(m0, rm0), nm1 = fmaxf(m1, rm1);
            float c0 = exp2f(m0 - nm0), c1 = exp2f(m1 - nm1);
            m0 = nm0; m1 = nm1;
            float rs0 = 0.0f, rs1 = 0.0f;
            #pragma unroll
            for (int t = 0; t < 8; t++) {
                s[t][0] = exp2f(s[t][0] - nm0);
                s[t][1] = exp2f(s[t][1] - nm0);
                s[t][2] = exp2f(s[t][2] - nm1);
                s[t][3] = exp2f(s[t][3] - nm1);
                rs0 += s[t][0] + s[t][1];
                rs1 += s[t][2] + s[t][3];
            }
            l0 = l0 * c0 + rs0;
            l1 = l1 * c1 + rs1;
            #pragma unroll
            for (int t = 0; t < 8; t++) {
                o[t][0] *= c0; o[t][1] *= c0;
                o[t][2] *= c1; o[t][3] *= c1;
            }

            #pragma unroll
            for (int ks = 0; ks < 4; ks++) {
                uint32_t pah[4], pal[4];
                #pragma unroll
                for (int half = 0; half < 2; half++) {
                    const float* ps = s[2 * ks + half];
                    __nv_bfloat16 h0, lo0, h1, lo1, h2, lo2, h3, lo3;
                    split1(ps[0], h0, lo0); split1(ps[1], h1, lo1);
                    split1(ps[2], h2, lo2); split1(ps[3], h3, lo3);
                    pah[half * 2 + 0] = pk2(h0, h1);  pal[half * 2 + 0] = pk2(lo0, lo1);
                    pah[half * 2 + 1] = pk2(h2, h3);  pal[half * 2 + 1] = pk2(lo2, lo3);
                }
                #pragma unroll
                for (int g2 = 0; g2 < 4; g2++) {
                    int row = ks * 16 + vrow;
                    uint32_t off = (uint32_t)(row * 8 + ((g2 * 2 + vcs) ^ (row & 7))) * 16;
                    uint32_t vb[4], vl2[4];
                    ldm4t(vb, aVh + off);
                    ldm4t(vl2, aVl + off);
                    #pragma unroll
                    for (int p = 0; p < 3; p++)
                        #pragma unroll
                        for (int hf = 0; hf < 2; hf++) {
                            const uint32_t* A = (p == 1) ? pal : pah;
                            const uint32_t* B = (p == 2) ? &vl2[hf * 2] : &vb[hf * 2];
                            mma16816(o[g2 * 2 + hf], A, B);
                        }
                }
            }
        }
    }

    l0 += __shfl_xor_sync(0xFFFFFFFFu, l0, 1);
    l0 += __shfl_xor_sync(0xFFFFFFFFu, l0, 2);
    l1 += __shfl_xor_sync(0xFFFFFFFFu, l1, 1);
    l1 += __shfl_xor_sync(0xFFFFFFFFu, l1, 2);
    float inv0 = 1.0f / l0, inv1 = 1.0f / l1;

    int r0 = qBase + wid * 16 + g;
    int r1 = r0 + 8;
    size_t o0 = ((size_t)(b * SS + r0) * NH + h) * DKH;
    size_t o1 = ((size_t)(b * SS + r1) * NH + h) * DKH;
    #pragma unroll
    for (int t = 0; t < 8; t++) {
        int d = 8 * t + 2 * tig;
        float v0 = o[t][0] * inv0, v1 = o[t][1] * inv0;
        float v2 = o[t][2] * inv1, v3 = o[t][3] * inv1;
        __nv_bfloat16 h0, lo0, h1, lo1, h2, lo2, h3, lo3;
        split1(v0, h0, lo0); split1(v1, h1, lo1);
        split1(v2, h2, lo2); split1(v3, h3, lo3);
        *(uint32_t*)(Oh + o0 + d) = pk2(h0, h1);
        *(uint32_t*)(Ol + o0 + d) = pk2(lo0, lo1);
        *(uint32_t*)(Oh + o1 + d) = pk2(h2, h3);
        *(uint32_t*)(Ol + o1 + d) = pk2(lo2, lo3);
    }
}

// ================= SwiGLU -> bf16 hi/lo =================
__global__ __launch_bounds__(256) void silu_split_kernel(const float4* __restrict__ g,
                                                         const float4* __restrict__ u,
                                                         uint2* __restrict__ oh,
                                                         uint2* __restrict__ ol, int n4) {
    int i = blockIdx.x * 256 + threadIdx.x;
    if (i >= n4) return;
    float4 a = g[i], bb = u[i];
    a.x = a.x / (1.0f + __expf(-a.x)) * bb.x;
    a.y = a.y / (1.0f + __expf(-a.y)) * bb.y;
    a.z = a.z / (1.0f + __expf(-a.z)) * bb.z;
    a.w = a.w / (1.0f + __expf(-a.w)) * bb.w;
    __nv_bfloat16 hx, lx, hy, ly, hz, lz, hw, lw;
    split1(a.x, hx, lx); split1(a.y, hy, ly);
    split1(a.z, hz, lz); split1(a.w, hw, lw);
    oh[i] = make_uint2(pk2(hx, hy), pk2(hz, hw));
    ol[i] = make_uint2(pk2(lx, ly), pk2(lz, lw));
}

extern "C" void kernel_launch(void* const* d_in, const int* in_sizes, int n_in,
                              void* d_out, int out_size) {
    const float* x   = (const float*)d_in[0];
    const float* ln1 = (const float*)d_in[1];
    const float* qw  = (const float*)d_in[2];
    const float* kw  = (const float*)d_in[3];
    const float* vw  = (const float*)d_in[4];
    const float* ow  = (const float*)d_in[5];
    const float* ln2 = (const float*)d_in[6];
    const float* w1  = (const float*)d_in[7];
    const float* w3  = (const float*)d_in[8];
    const float* w2  = (const float*)d_in[9];
    const int*   pos = (const int*)d_in[10];
    float* out = (float*)d_out;

    float *x1, *gt, *up;
    cudaGetSymbolAddress((void**)&x1, g_x1);
    cudaGetSymbolAddress((void**)&gt, g_gt);
    cudaGetSymbolAddress((void**)&up, g_up);
    __nv_bfloat16 *qh_, *ql_, *kh_, *kl_, *vh_, *vl_;
    cudaGetSymbolAddress((void**)&qh_, g_qh); cudaGetSymbolAddress((void**)&ql_, g_ql);
    cudaGetSymbolAddress((void**)&kh_, g_kh); cudaGetSymbolAddress((void**)&kl_, g_kl);
    cudaGetSymbolAddress((void**)&vh_, g_vh); cudaGetSymbolAddress((void**)&vl_, g_vl);
    __nv_bfloat16 *hh, *hl, *cxh, *cxl, *glh, *gll;
    __nv_bfloat16 *wqh, *wql, *wkh, *wkl, *wvh, *wvl, *woh, *wol;
    __nv_bfloat16 *w1h, *w1l, *w3h, *w3l, *w2h, *w2l;
    cudaGetSymbolAddress((void**)&hh,  g_h_h);  cudaGetSymbolAddress((void**)&hl,  g_h_l);
    cudaGetSymbolAddress((void**)&cxh, g_cx_h); cudaGetSymbolAddress((void**)&cxl, g_cx_l);
    cudaGetSymbolAddress((void**)&glh, g_gl_h); cudaGetSymbolAddress((void**)&gll, g_gl_l);
    cudaGetSymbolAddress((void**)&wqh, g_wq_h); cudaGetSymbolAddress((void**)&wql, g_wq_l);
    cudaGetSymbolAddress((void**)&wkh, g_wk_h); cudaGetSymbolAddress((void**)&wkl, g_wk_l);
    cudaGetSymbolAddress((void**)&wvh, g_wv_h); cudaGetSymbolAddress((void**)&wvl, g_wv_l);
    cudaGetSymbolAddress((void**)&woh, g_wo_h); cudaGetSymbolAddress((void**)&wol, g_wo_l);
    cudaGetSymbolAddress((void**)&w1h, g_w1_h); cudaGetSymbolAddress((void**)&w1l, g_w1_l);
    cudaGetSymbolAddress((void**)&w3h, g_w3_h); cudaGetSymbolAddress((void**)&w3l, g_w3_l);
    cudaGetSymbolAddress((void**)&w2h, g_w2_h); cudaGetSymbolAddress((void**)&w2l, g_w2_l);

    cudaFuncSetAttribute(mma_gemm<0>, cudaFuncAttributeMaxDynamicSharedMemorySize, GSMEM);
    cudaFuncSetAttribute(mma_gemm<1>, cudaFuncAttributeMaxDynamicSharedMemorySize, GSMEM);
    cudaFuncSetAttribute(mma_gemm_qkv, cudaFuncAttributeMaxDynamicSharedMemorySize, GSMEM);
    cudaFuncSetAttribute(attn_mma, cudaFuncAttributeMaxDynamicSharedMemorySize, 65536);

    const int n4_mm = DM * DM / 4, n4_ff = DFF * DM / 4;
    split4_kernel<<<dim3((n4_mm + 1023) / 1024, 4), 256>>>(
        (const float4*)qw, (const float4*)kw, (const float4*)vw, (const float4*)ow,
        (uint2*)wqh, (uint2*)wql, (uint2*)wkh, (uint2*)wkl,
        (uint2*)wvh, (uint2*)wvl, (uint2*)woh, (uint2*)wol, n4_mm);
    split3_kernel<<<dim3((n4_ff + 1023) / 1024, 3), 256>>>(
        (const float4*)w1, (const float4*)w3, (const float4*)w2,
        (uint2*)w1h, (uint2*)w1l, (uint2*)w3h, (uint2*)w3l, (uint2*)w2h, (uint2*)w2l, n4_ff);

    dim3 gqkv(DM / 128, ROWS / 128, 3);   // (8, 32, 3)
    dim3 gq1 (DM / 128, ROWS / 128, 1);   // (8, 32)
    dim3 gf2 (DFF / 128, ROWS / 128, 2);  // (21, 32, 2)
    dim3 ga  (SS / 128, BB * NH);         // (16, 32)

    rmsnorm_split_kernel<<<ROWS, 256>>>(x, ln1, hh, hl);
    mma_gemm_qkv<<<gqkv, 512, GSMEM>>>(hh, hl, wqh, wql, wkh, wkl, wvh, wvl, pos,
                                       qh_, ql_, kh_, kl_, vh_, vl_, ROWS, DM, DM);
    attn_mma<<<ga, 256, 65536>>>(qh_, ql_, kh_, kl_, vh_, vl_, cxh, cxl);
    mma_gemm<1><<<gq1, 512, GSMEM>>>(cxh, cxl, woh, wol, nullptr, nullptr,
                                     x, x1, nullptr, ROWS, DM, DM);
    rmsnorm_split_kernel<<<ROWS, 256>>>(x1, ln2, hh, hl);
    mma_gemm<0><<<gf2, 512, GSMEM>>>(hh, hl, w1h, w1l, w3h, w3l,
                                     nullptr, gt, up, ROWS, DFF, DM);
    silu_split_kernel<<<(ROWS * DFF / 4 + 255) / 256, 256>>>((const float4*)gt, (const float4*)up,
                                                             (uint2*)glh, (uint2*)gll, ROWS * DFF / 4);
    mma_gemm<1><<<gq1, 512, GSMEM>>>(glh, gll, w2h, w2l, nullptr, nullptr,
                                     x1, out, nullptr, ROWS, DM, DFF);
}